// round 3
// baseline (speedup 1.0000x reference)
#include <cuda_runtime.h>
#include <cuda_bf16.h>
#include <math.h>
#include <cfloat>
#include <cstdint>

// ===========================================================================
// MIL-NCE head: s = (v @ t^T)/0.1, N=4096, T=4, D=256 (NT=16384)
// Outputs: [loss, recall1, recall5, recall10, avg_rank]
//
//  K0 init   : rmax/cmax <- -inf, cnt <- 0
//  K1 split  : fp32 -> 3x bf16 splits of v and t
//  K2 gemm   : mma.sync bf16 6-product GEMM (fp32-accurate), S -> scratch,
//              exact row/col maxes via deterministic atomicMax
//  K3 stats  : one pass over S: rank counts (ballot/popc), row sumexp
//              partials, col sumexp partials (threshold-gated exp)
//  K4 rowfin : per-row LSE combine + metrics
//  K5 reduce : deterministic means
// ===========================================================================

namespace {
constexpr int N  = 4096;
constexpr int T  = 4;
constexpr int NT = 16384;
constexpr int D  = 256;
constexpr float SCALE   = 10.0f;
constexpr float LSE_CUT = 30.0f;

constexpr int BM = 128, BN = 128;
constexpr int KC = 64;                      // K chunk: 64 bf16 = 128B rows (SW128)
constexpr int NCHUNK = D / KC;              // 4
constexpr int CTILE = NT / BN;              // 128
constexpr int RTILE = N / BM;               // 32

constexpr int NA = N * D;
constexpr int NB = NT * D;

constexpr int TILE_B    = BM * KC * 2;      // 16384 bytes per split tile
constexpr int GEMM_SMEM = 6 * TILE_B;       // 98304
}

// ------------------------- device scratch ---------------------------------
__device__ float          g_S[(size_t)N * NT];   // 256 MB
__device__ __nv_bfloat16  g_As[3][NA];
__device__ __nv_bfloat16  g_Bs[3][NB];
__device__ int            g_rmax[N];
__device__ int            g_cmax[NT];
__device__ int            g_cnt[N][T];
__device__ float          g_cpart[RTILE][NT];
__device__ float          g_rspart[CTILE][N];
__device__ float          g_rowout[N][5];

// ------------------------- helpers ----------------------------------------
__device__ __forceinline__ int enc_f(float f) {
    int i = __float_as_int(f);
    return i >= 0 ? i : i ^ 0x7fffffff;
}
__device__ __forceinline__ float dec_f(int i) {
    return __int_as_float(i >= 0 ? i : i ^ 0x7fffffff);
}
__device__ __forceinline__ uint32_t smem_u32(const void* p) {
    uint32_t a;
    asm("{ .reg .u64 t; cvta.to.shared.u64 t, %1; cvt.u32.u64 %0, t; }" : "=r"(a) : "l"(p));
    return a;
}
__device__ __forceinline__ uint32_t sw128(uint32_t b) { return b ^ ((b >> 3) & 0x70); }

__device__ __forceinline__ void ldsm4(uint32_t* r, uint32_t addr) {
    asm volatile("ldmatrix.sync.aligned.m8n8.x4.shared.b16 {%0,%1,%2,%3}, [%4];"
        : "=r"(r[0]), "=r"(r[1]), "=r"(r[2]), "=r"(r[3]) : "r"(addr));
}
__device__ __forceinline__ void mma_bf16(float* d, const uint32_t* a, uint32_t b0, uint32_t b1) {
    asm volatile("mma.sync.aligned.m16n8k16.row.col.f32.bf16.bf16.f32 "
        "{%0,%1,%2,%3}, {%4,%5,%6,%7}, {%8,%9}, {%0,%1,%2,%3};"
        : "+f"(d[0]), "+f"(d[1]), "+f"(d[2]), "+f"(d[3])
        : "r"(a[0]), "r"(a[1]), "r"(a[2]), "r"(a[3]), "r"(b0), "r"(b1));
}

// ===========================================================================
// K0: init
__global__ void init_kernel() {
    int i = blockIdx.x * 256 + threadIdx.x;
    if (i < N)  g_rmax[i] = (int)0x80000000;
    if (i < NT) {
        g_cmax[i] = (int)0x80000000;
        g_cnt[i >> 2][i & 3] = 0;
    }
}

// ===========================================================================
// K1: 3-way bf16 split
__global__ __launch_bounds__(256)
void split_kernel(const float* __restrict__ v, const float* __restrict__ t) {
    int i = blockIdx.x * 256 + threadIdx.x;
    if (i >= NA + NB) return;
    float a = (i < NA) ? v[i] : t[i - NA];
    __nv_bfloat16 h0 = __float2bfloat16(a);
    float r1 = a - __bfloat162float(h0);
    __nv_bfloat16 h1 = __float2bfloat16(r1);
    float r2 = r1 - __bfloat162float(h1);
    __nv_bfloat16 h2 = __float2bfloat16(r2);
    if (i < NA) { g_As[0][i] = h0; g_As[1][i] = h1; g_As[2][i] = h2; }
    else { int j = i - NA; g_Bs[0][j] = h0; g_Bs[1][j] = h1; g_Bs[2][j] = h2; }
}

// ===========================================================================
// K2: HMMA GEMM. Block tile 128x128, 8 warps as 4(m) x 2(n): warp tile 32x64.
// 6 bf16 split-products accumulate into one fp32 accumulator set.
__global__ __launch_bounds__(256, 2)
void gemm_mma() {
    extern __shared__ char smem[];
    const uint32_t sb = smem_u32(smem);
    const int tid = threadIdx.x, lane = tid & 31, wid = tid >> 5;
    const int wm = wid >> 1, wn = wid & 1;        // warp grid 4m x 2n
    const int bn = blockIdx.x, bm = blockIdx.y;

    // ldmatrix per-lane addressing (SW128-swizzled, 128B rows)
    // A (x4 covering m16 x k16): row_in_frag = lane&15, k-halfbyte = (lane>>4)*16
    const int a_r   = lane & 15;
    const int a_koff = (lane >> 4) * 16;
    // B (x4 covering n16 x k16): nrow = (lane&7) + ((lane&16)>>1), koff = (lane&8)*2
    const int b_r   = (lane & 7) + ((lane & 16) >> 1);
    const int b_koff = (lane & 8) << 1;
    const uint32_t a_xm = (uint32_t)(a_r & 7) << 4;
    const uint32_t b_xm = (uint32_t)(b_r & 7) << 4;

    // per-frag row byte offsets within a tile
    uint32_t a_rowb[2], b_rowb[4];
    #pragma unroll
    for (int mi = 0; mi < 2; mi++) a_rowb[mi] = (uint32_t)(wm * 32 + mi * 16 + a_r) * 128;
    #pragma unroll
    for (int p = 0; p < 4; p++)    b_rowb[p]  = (uint32_t)(wn * 64 + p * 16 + b_r) * 128;

    float acc[2][8][4];
    #pragma unroll
    for (int mi = 0; mi < 2; mi++)
        #pragma unroll
        for (int nf = 0; nf < 8; nf++)
            #pragma unroll
            for (int q = 0; q < 4; q++) acc[mi][nf][q] = 0.f;

    const int PA[6] = {0, 0, 1, 1, 0, 2};
    const int PB[6] = {0, 1, 0, 1, 2, 0};

    for (int kc = 0; kc < NCHUNK; kc++) {
        const int k0 = kc * KC;
        // load 6 split tiles (128 x 64 bf16 each), SW128-swizzled
        #pragma unroll
        for (int i = 0; i < 24; i++) {
            int g = i * 256 + tid;
            int s = g >> 10;
            int idx = g & 1023;
            int r = idx >> 3, b = idx & 7;
            const __nv_bfloat16* src =
                (s < 3) ? (g_As[s]     + (size_t)(bm * BM + r) * D + k0 + b * 8)
                        : (g_Bs[s - 3] + (size_t)(bn * BN + r) * D + k0 + b * 8);
            uint4 val = *reinterpret_cast<const uint4*>(src);
            *reinterpret_cast<uint4*>(smem + s * TILE_B + sw128(r * 128 + b * 16)) = val;
        }
        __syncthreads();

        #pragma unroll
        for (int s6 = 0; s6 < 6; s6++) {
            const uint32_t aBase = sb + PA[s6] * TILE_B;
            const uint32_t bBase = sb + (3 + PB[s6]) * TILE_B;
            #pragma unroll
            for (int k16 = 0; k16 < 4; k16++) {
                const uint32_t kb = k16 * 32;
                uint32_t afr[2][4];
                #pragma unroll
                for (int mi = 0; mi < 2; mi++)
                    ldsm4(afr[mi], aBase + a_rowb[mi] + ((kb + a_koff) ^ a_xm));
                uint32_t bfr[4][4];
                #pragma unroll
                for (int p = 0; p < 4; p++)
                    ldsm4(bfr[p], bBase + b_rowb[p] + ((kb + b_koff) ^ b_xm));
                #pragma unroll
                for (int mi = 0; mi < 2; mi++)
                    #pragma unroll
                    for (int nf = 0; nf < 8; nf++)
                        mma_bf16(acc[mi][nf], afr[mi], bfr[nf >> 1][(nf & 1) * 2],
                                 bfr[nf >> 1][(nf & 1) * 2 + 1]);
            }
        }
        __syncthreads();
    }

    // ---- epilogue: scale, store S, exact row/col maxes ----
    #pragma unroll
    for (int mi = 0; mi < 2; mi++)
        #pragma unroll
        for (int nf = 0; nf < 8; nf++)
            #pragma unroll
            for (int q = 0; q < 4; q++) acc[mi][nf][q] *= SCALE;

    const int qr = lane >> 2;           // 0..7
    const int qc = (lane & 3) * 2;      // 0,2,4,6

    // store (float2 per n8 frag per row-slot)
    #pragma unroll
    for (int mi = 0; mi < 2; mi++)
        #pragma unroll
        for (int h = 0; h < 2; h++) {
            int row = bm * BM + wm * 32 + mi * 16 + h * 8 + qr;
            float* dst = g_S + (size_t)row * NT + (size_t)bn * BN + wn * 64 + qc;
            #pragma unroll
            for (int nf = 0; nf < 8; nf++)
                *reinterpret_cast<float2*>(dst + nf * 8) =
                    make_float2(acc[mi][nf][2 * h], acc[mi][nf][2 * h + 1]);
        }

    // row maxes: reduce over this thread's cols, then across lanes sharing qr
    #pragma unroll
    for (int mi = 0; mi < 2; mi++)
        #pragma unroll
        for (int h = 0; h < 2; h++) {
            float m = -FLT_MAX;
            #pragma unroll
            for (int nf = 0; nf < 8; nf++)
                m = fmaxf(m, fmaxf(acc[mi][nf][2 * h], acc[mi][nf][2 * h + 1]));
            m = fmaxf(m, __shfl_xor_sync(0xffffffffu, m, 1));
            m = fmaxf(m, __shfl_xor_sync(0xffffffffu, m, 2));
            if ((lane & 3) == 0)
                atomicMax(&g_rmax[bm * BM + wm * 32 + mi * 16 + h * 8 + qr], enc_f(m));
        }

    // col maxes: reduce over row-slots, then across lanes sharing qc
    #pragma unroll
    for (int nf = 0; nf < 8; nf++) {
        float m0 = -FLT_MAX, m1 = -FLT_MAX;
        #pragma unroll
        for (int mi = 0; mi < 2; mi++) {
            m0 = fmaxf(m0, fmaxf(acc[mi][nf][0], acc[mi][nf][2]));
            m1 = fmaxf(m1, fmaxf(acc[mi][nf][1], acc[mi][nf][3]));
        }
        #pragma unroll
        for (int off = 4; off < 32; off <<= 1) {
            m0 = fmaxf(m0, __shfl_xor_sync(0xffffffffu, m0, off));
            m1 = fmaxf(m1, __shfl_xor_sync(0xffffffffu, m1, off));
        }
        if (lane < 4) {
            int col = bn * BN + wn * 64 + nf * 8 + qc;
            atomicMax(&g_cmax[col],     enc_f(m0));
            atomicMax(&g_cmax[col + 1], enc_f(m1));
        }
    }
}

// ===========================================================================
// K3: fused stats pass — one read of S.
__global__ __launch_bounds__(256)
void stats_kernel() {
    __shared__ float sp[128][4];
    __shared__ float srm[128];
    __shared__ float sthr[128];
    __shared__ int   scnt[8][128][4];
    __shared__ float srs[8][128];
    __shared__ float scs[256];

    const int tid = threadIdx.x, w = tid >> 5, lane = tid & 31;
    const int ct = blockIdx.x, rt = blockIdx.y;
    const int c0 = ct * BN, r0 = rt * BM;

    if (tid < 128) {
        int gr = r0 + tid;
        float rm = dec_f(g_rmax[gr]);
        srm[tid] = rm;
        sthr[tid] = rm - LSE_CUT;
        #pragma unroll
        for (int t = 0; t < 4; t++)
            sp[tid][t] = g_S[(size_t)gr * NT + gr * 4 + t];
    }
    for (int i = tid; i < 8 * 128 * 4; i += 256) ((int*)scnt)[i] = 0;
    for (int i = tid; i < 8 * 128; i += 256) ((float*)srs)[i] = 0.f;
    __syncthreads();

    const int col  = c0 + (tid & 127);
    const int half = tid >> 7;
    const float cm   = dec_f(g_cmax[col]);
    const float cthr = cm - LSE_CUT;
    float csum = 0.f;
    const float* Sp = g_S + (size_t)(r0 + half * 64) * NT + col;

    for (int rr = 0; rr < 64; rr++) {
        const int r = half * 64 + rr;
        const float x = Sp[(size_t)rr * NT];
        if (x > cthr) csum += expf(x - cm);
        #pragma unroll
        for (int t = 0; t < 4; t++) {
            const float pv = sp[r][t];
            const int   pc = (r0 + r) * 4 + t;
            bool pred = (x > pv) || (x == pv && col < pc);
            unsigned bal = __ballot_sync(0xffffffffu, pred);
            if (lane == 0) scnt[w][r][t] += __popc(bal);
        }
        bool e = x > sthr[r];
        unsigned bal2 = __ballot_sync(0xffffffffu, e);
        if (bal2) {
            float vv = e ? expf(x - srm[r]) : 0.f;
            #pragma unroll
            for (int off = 16; off; off >>= 1)
                vv += __shfl_xor_sync(0xffffffffu, vv, off);
            if (lane == 0) srs[w][r] += vv;
        }
    }
    scs[tid] = csum;
    __syncthreads();

    if (tid < 128) {
        g_cpart[rt][c0 + tid] = scs[tid] + scs[tid + 128];
        const int r = tid;
        #pragma unroll
        for (int t = 0; t < 4; t++) {
            int c = 0;
            #pragma unroll
            for (int ww = 0; ww < 8; ww++) c += scnt[ww][r][t];
            atomicAdd(&g_cnt[r0 + r][t], c);
        }
        float rs = 0.f;
        #pragma unroll
        for (int ww = 0; ww < 8; ww++) rs += srs[ww][r];
        g_rspart[ct][r0 + r] = rs;
    }
}

// ===========================================================================
// K4: per-row finalize
__global__ __launch_bounds__(256)
void rowfin_kernel() {
    int i = blockIdx.x * 256 + threadIdx.x;
    if (i >= N) return;

    float p[4];
    #pragma unroll
    for (int t = 0; t < 4; t++) p[t] = g_S[(size_t)i * NT + i * 4 + t];
    float rm = dec_f(g_rmax[i]);

    float rsum = 0.f;
    for (int ct = 0; ct < CTILE; ct++) rsum += g_rspart[ct][i];

    float pm = fmaxf(fmaxf(p[0], p[1]), fmaxf(p[2], p[3]));
    float nom = pm + logf(expf(p[0] - pm) + expf(p[1] - pm) +
                          expf(p[2] - pm) + expf(p[3] - pm));

    float cmv[4], M = rm;
    #pragma unroll
    for (int t = 0; t < 4; t++) {
        cmv[t] = dec_f(g_cmax[i * 4 + t]);
        M = fmaxf(M, cmv[t]);
    }
    float tot = rsum * expf(rm - M);
    #pragma unroll
    for (int t = 0; t < 4; t++) {
        float cs = 0.f;
        for (int rt = 0; rt < RTILE; rt++) cs += g_cpart[rt][i * 4 + t];
        tot += cs * expf(cmv[t] - M);
    }
    float denom = M + logf(tot);

    float r1 = 0.f, r5 = 0.f, r10 = 0.f, ar = 0.f;
    #pragma unroll
    for (int t = 0; t < 4; t++) {
        int rk = g_cnt[i][t];
        r1  += (rk < 1);
        r5  += (rk < 5);
        r10 += (rk < 10);
        ar  += (float)rk;
    }
    g_rowout[i][0] = denom - nom;
    g_rowout[i][1] = r1  * 0.25f;
    g_rowout[i][2] = r5  * 0.25f;
    g_rowout[i][3] = r10 * 0.25f;
    g_rowout[i][4] = ar  * 0.25f;
}

// ===========================================================================
// K5: deterministic means
__global__ __launch_bounds__(256)
void final_kernel(float* __restrict__ out) {
    __shared__ double sacc[5][256];
    int tid = threadIdx.x;
    double a[5] = {0, 0, 0, 0, 0};
    for (int i = tid; i < N; i += 256)
        #pragma unroll
        for (int q = 0; q < 5; q++) a[q] += (double)g_rowout[i][q];
    #pragma unroll
    for (int q = 0; q < 5; q++) sacc[q][tid] = a[q];
    __syncthreads();
    for (int off = 128; off > 0; off >>= 1) {
        if (tid < off)
            #pragma unroll
            for (int q = 0; q < 5; q++) sacc[q][tid] += sacc[q][tid + off];
        __syncthreads();
    }
    if (tid == 0)
        #pragma unroll
        for (int q = 0; q < 5; q++) out[q] = (float)(sacc[q][0] / (double)N);
}

// ===========================================================================
extern "C" void kernel_launch(void* const* d_in, const int* in_sizes, int n_in,
                              void* d_out, int out_size) {
    const float* v = (const float*)d_in[0];   // [4096, 256]
    const float* t = (const float*)d_in[1];   // [16384, 256]
    (void)in_sizes; (void)n_in; (void)out_size;

    static int attr_done = 0;
    if (!attr_done) {
        cudaFuncSetAttribute(gemm_mma, cudaFuncAttributeMaxDynamicSharedMemorySize, GEMM_SMEM);
        attr_done = 1;
    }

    init_kernel<<<(NT + 255) / 256, 256>>>();
    split_kernel<<<(NA + NB + 255) / 256, 256>>>(v, t);
    gemm_mma<<<dim3(CTILE, RTILE), 256, GEMM_SMEM>>>();
    stats_kernel<<<dim3(CTILE, RTILE), 256>>>();
    rowfin_kernel<<<(N + 255) / 256, 256>>>();
    final_kernel<<<1, 256>>>((float*)d_out);
}

// round 4
// speedup vs baseline: 2.6265x; 2.6265x over previous
#include <cuda_runtime.h>
#include <cuda_bf16.h>
#include <math.h>
#include <cfloat>
#include <cstdint>

// ===========================================================================
// MIL-NCE head: s = (v @ t^T)/0.1, N=4096, T=4, D=256 (NT=16384)
// Outputs: [loss, recall1, recall5, recall10, avg_rank]
//
//  K0 init   : rmax/cmax <- -inf, cnt <- 0
//  K1 split  : fp32 -> 2x bf16 splits of v and t
//  K2 gemm   : mma.sync bf16 3-product GEMM, cp.async double-buffered,
//              S -> scratch, exact row/col maxes (deterministic atomicMax)
//  K3 stats  : smem-staged block pass: rank counts (register adds),
//              row/col sumexp partials (threshold-gated exp)
//  K4 rowfin : per-row LSE combine + metrics
//  K5 reduce : deterministic means
// ===========================================================================

namespace {
constexpr int N  = 4096;
constexpr int T  = 4;
constexpr int NT = 16384;
constexpr int D  = 256;
constexpr float SCALE   = 10.0f;
constexpr float LSE_CUT = 30.0f;

constexpr int BM = 128, BN = 128;
constexpr int KC = 64;                      // K chunk: 64 bf16 = 128B rows (SW128)
constexpr int NCHUNK = D / KC;              // 4
constexpr int CTILE = NT / BN;              // 128
constexpr int RTILE = N / BM;               // 32

constexpr int NA = N * D;
constexpr int NB = NT * D;

constexpr int TILE_B    = BM * KC * 2;      // 16384 bytes per split tile
constexpr int STAGE_B   = 4 * TILE_B;       // A0,A1,B0,B1 = 65536
constexpr int GEMM_SMEM = 2 * STAGE_B;      // 131072 (double buffer)

constexpr int SPAD = 132;                   // stats tile row pitch (words), 16B-aligned
constexpr int STAT_SMEM = 128 * SPAD * 4;   // 67584
}

// ------------------------- device scratch ---------------------------------
__device__ float          g_S[(size_t)N * NT];   // 256 MB
__device__ __nv_bfloat16  g_As[2][NA];
__device__ __nv_bfloat16  g_Bs[2][NB];
__device__ int            g_rmax[N];
__device__ int            g_cmax[NT];
__device__ int            g_cnt[N][T];
__device__ float          g_cpart[RTILE][NT];
__device__ float          g_rspart[CTILE][N];
__device__ float          g_rowout[N][5];

// ------------------------- helpers ----------------------------------------
__device__ __forceinline__ int enc_f(float f) {
    int i = __float_as_int(f);
    return i >= 0 ? i : i ^ 0x7fffffff;
}
__device__ __forceinline__ float dec_f(int i) {
    return __int_as_float(i >= 0 ? i : i ^ 0x7fffffff);
}
__device__ __forceinline__ uint32_t smem_u32(const void* p) {
    uint32_t a;
    asm("{ .reg .u64 t; cvta.to.shared.u64 t, %1; cvt.u32.u64 %0, t; }" : "=r"(a) : "l"(p));
    return a;
}
__device__ __forceinline__ uint32_t sw128(uint32_t b) { return b ^ ((b >> 3) & 0x70); }

__device__ __forceinline__ void ldsm4(uint32_t* r, uint32_t addr) {
    asm volatile("ldmatrix.sync.aligned.m8n8.x4.shared.b16 {%0,%1,%2,%3}, [%4];"
        : "=r"(r[0]), "=r"(r[1]), "=r"(r[2]), "=r"(r[3]) : "r"(addr));
}
__device__ __forceinline__ void mma_bf16(float* d, const uint32_t* a, uint32_t b0, uint32_t b1) {
    asm volatile("mma.sync.aligned.m16n8k16.row.col.f32.bf16.bf16.f32 "
        "{%0,%1,%2,%3}, {%4,%5,%6,%7}, {%8,%9}, {%0,%1,%2,%3};"
        : "+f"(d[0]), "+f"(d[1]), "+f"(d[2]), "+f"(d[3])
        : "r"(a[0]), "r"(a[1]), "r"(a[2]), "r"(a[3]), "r"(b0), "r"(b1));
}
__device__ __forceinline__ void cp16(uint32_t dst, const void* src) {
    asm volatile("cp.async.cg.shared.global [%0], [%1], 16;" :: "r"(dst), "l"(src));
}
#define CP_COMMIT() asm volatile("cp.async.commit_group;" ::: "memory")
#define CP_WAIT(n)  asm volatile("cp.async.wait_group %0;" :: "n"(n) : "memory")

// ===========================================================================
// K0: init
__global__ void init_kernel() {
    int i = blockIdx.x * 256 + threadIdx.x;
    if (i < N)  g_rmax[i] = (int)0x80000000;
    if (i < NT) {
        g_cmax[i] = (int)0x80000000;
        g_cnt[i >> 2][i & 3] = 0;
    }
}

// ===========================================================================
// K1: 2-way bf16 split
__global__ __launch_bounds__(256)
void split_kernel(const float* __restrict__ v, const float* __restrict__ t) {
    int i = blockIdx.x * 256 + threadIdx.x;
    if (i >= NA + NB) return;
    float a = (i < NA) ? v[i] : t[i - NA];
    __nv_bfloat16 h0 = __float2bfloat16(a);
    float r1 = a - __bfloat162float(h0);
    __nv_bfloat16 h1 = __float2bfloat16(r1);
    if (i < NA) { g_As[0][i] = h0; g_As[1][i] = h1; }
    else { int j = i - NA; g_Bs[0][j] = h0; g_Bs[1][j] = h1; }
}

// ===========================================================================
// K2: HMMA GEMM, 3 split-products, cp.async double-buffered.
// Block tile 128x128, 8 warps as 4(m) x 2(n): warp tile 32x64.
__global__ __launch_bounds__(256, 1)
void gemm_mma() {
    extern __shared__ char smem[];
    const uint32_t sb = smem_u32(smem);
    const int tid = threadIdx.x, lane = tid & 31, wid = tid >> 5;
    const int wm = wid >> 1, wn = wid & 1;
    const int bn = blockIdx.x, bm = blockIdx.y;

    // ldmatrix per-lane addressing (SW128, 128B rows) — as validated in R3
    const int a_r    = lane & 15;
    const int a_koff = (lane >> 4) * 16;
    const int b_r    = (lane & 7) + ((lane & 16) >> 1);
    const int b_koff = (lane & 8) << 1;
    const uint32_t a_xm = (uint32_t)(a_r & 7) << 4;
    const uint32_t b_xm = (uint32_t)(b_r & 7) << 4;

    uint32_t a_rowb[2], b_rowb[4];
    #pragma unroll
    for (int mi = 0; mi < 2; mi++) a_rowb[mi] = (uint32_t)(wm * 32 + mi * 16 + a_r) * 128;
    #pragma unroll
    for (int p = 0; p < 4; p++)    b_rowb[p]  = (uint32_t)(wn * 64 + p * 16 + b_r) * 128;

    float acc[2][8][4];
    #pragma unroll
    for (int mi = 0; mi < 2; mi++)
        #pragma unroll
        for (int nf = 0; nf < 8; nf++)
            #pragma unroll
            for (int q = 0; q < 4; q++) acc[mi][nf][q] = 0.f;

    // ---- prefetch helper: stage has tiles A0,A1,B0,B1 (16KB each) ----
    auto prefetch = [&](int stage, int kc) {
        const int k0 = kc * KC;
        #pragma unroll
        for (int i = 0; i < 16; i++) {
            int g = i * 256 + tid;          // 0..4095 16B-chunks
            int s = g >> 10;                // tile id
            int idx = g & 1023;
            int r = idx >> 3, b = idx & 7;
            const __nv_bfloat16* src =
                (s < 2) ? (g_As[s]     + (size_t)(bm * BM + r) * D + k0 + b * 8)
                        : (g_Bs[s - 2] + (size_t)(bn * BN + r) * D + k0 + b * 8);
            cp16(sb + stage * STAGE_B + s * TILE_B + sw128(r * 128 + b * 16), src);
        }
    };

    prefetch(0, 0);
    CP_COMMIT();

    for (int kc = 0; kc < NCHUNK; kc++) {
        if (kc < NCHUNK - 1) { prefetch((kc + 1) & 1, kc + 1); CP_COMMIT(); }
        if (kc < NCHUNK - 1) { CP_WAIT(1); } else { CP_WAIT(0); }
        __syncthreads();

        const uint32_t base = sb + (kc & 1) * STAGE_B;
        #pragma unroll
        for (int k16 = 0; k16 < 4; k16++) {
            const uint32_t kb = k16 * 32;
            uint32_t afr[2][2][4];   // [split][mi]
            #pragma unroll
            for (int s2 = 0; s2 < 2; s2++)
                #pragma unroll
                for (int mi = 0; mi < 2; mi++)
                    ldsm4(afr[s2][mi], base + s2 * TILE_B + a_rowb[mi] + ((kb + a_koff) ^ a_xm));
            uint32_t bfr[2][4][4];   // [split][p]
            #pragma unroll
            for (int s2 = 0; s2 < 2; s2++)
                #pragma unroll
                for (int p = 0; p < 4; p++)
                    ldsm4(bfr[s2][p], base + (2 + s2) * TILE_B + b_rowb[p] + ((kb + b_koff) ^ b_xm));

            // products: (0,0), (0,1), (1,0)
            #pragma unroll
            for (int mi = 0; mi < 2; mi++)
                #pragma unroll
                for (int nf = 0; nf < 8; nf++) {
                    const uint32_t* bp0 = &bfr[0][nf >> 1][(nf & 1) * 2];
                    const uint32_t* bp1 = &bfr[1][nf >> 1][(nf & 1) * 2];
                    mma_bf16(acc[mi][nf], afr[0][mi], bp0[0], bp0[1]);
                    mma_bf16(acc[mi][nf], afr[0][mi], bp1[0], bp1[1]);
                    mma_bf16(acc[mi][nf], afr[1][mi], bp0[0], bp0[1]);
                }
        }
        __syncthreads();
    }

    // ---- epilogue: scale, store S, exact row/col maxes ----
    #pragma unroll
    for (int mi = 0; mi < 2; mi++)
        #pragma unroll
        for (int nf = 0; nf < 8; nf++)
            #pragma unroll
            for (int q = 0; q < 4; q++) acc[mi][nf][q] *= SCALE;

    const int qr = lane >> 2;
    const int qc = (lane & 3) * 2;

    #pragma unroll
    for (int mi = 0; mi < 2; mi++)
        #pragma unroll
        for (int h = 0; h < 2; h++) {
            int row = bm * BM + wm * 32 + mi * 16 + h * 8 + qr;
            float* dst = g_S + (size_t)row * NT + (size_t)bn * BN + wn * 64 + qc;
            #pragma unroll
            for (int nf = 0; nf < 8; nf++)
                *reinterpret_cast<float2*>(dst + nf * 8) =
                    make_float2(acc[mi][nf][2 * h], acc[mi][nf][2 * h + 1]);
        }

    #pragma unroll
    for (int mi = 0; mi < 2; mi++)
        #pragma unroll
        for (int h = 0; h < 2; h++) {
            float m = -FLT_MAX;
            #pragma unroll
            for (int nf = 0; nf < 8; nf++)
                m = fmaxf(m, fmaxf(acc[mi][nf][2 * h], acc[mi][nf][2 * h + 1]));
            m = fmaxf(m, __shfl_xor_sync(0xffffffffu, m, 1));
            m = fmaxf(m, __shfl_xor_sync(0xffffffffu, m, 2));
            if ((lane & 3) == 0)
                atomicMax(&g_rmax[bm * BM + wm * 32 + mi * 16 + h * 8 + qr], enc_f(m));
        }

    #pragma unroll
    for (int nf = 0; nf < 8; nf++) {
        float m0 = -FLT_MAX, m1 = -FLT_MAX;
        #pragma unroll
        for (int mi = 0; mi < 2; mi++) {
            m0 = fmaxf(m0, fmaxf(acc[mi][nf][0], acc[mi][nf][2]));
            m1 = fmaxf(m1, fmaxf(acc[mi][nf][1], acc[mi][nf][3]));
        }
        #pragma unroll
        for (int off = 4; off < 32; off <<= 1) {
            m0 = fmaxf(m0, __shfl_xor_sync(0xffffffffu, m0, off));
            m1 = fmaxf(m1, __shfl_xor_sync(0xffffffffu, m1, off));
        }
        if (lane < 4) {
            int col = bn * BN + wn * 64 + nf * 8 + qc;
            atomicMax(&g_cmax[col],     enc_f(m0));
            atomicMax(&g_cmax[col + 1], enc_f(m1));
        }
    }
}

// ===========================================================================
// K3: stats — stage 128x128 block in smem, then register-accumulated
// row sub-pass (rank counts + row sumexp) and col sub-pass (col sumexp).
__global__ __launch_bounds__(256)
void stats_kernel() {
    extern __shared__ float tile[];          // [128][SPAD]
    __shared__ float sp[128][4];
    __shared__ float srm[128], sthr[128];
    __shared__ int   scnt2[2][128][4];
    __shared__ float srs2[2][128];
    __shared__ float scs2[2][128];

    const int tid = threadIdx.x;
    const int ct = blockIdx.x, rt = blockIdx.y;
    const int c0 = ct * BN, r0 = rt * BM;

    // stage block (coalesced float4) + per-row constants
    #pragma unroll
    for (int i = 0; i < 16; i++) {
        int idx = i * 256 + tid;             // 0..4095 float4 chunks
        int r = idx >> 5, c4 = idx & 31;
        float4 v = *reinterpret_cast<const float4*>(
            g_S + (size_t)(r0 + r) * NT + c0 + c4 * 4);
        *reinterpret_cast<float4*>(&tile[r * SPAD + c4 * 4]) = v;
    }
    if (tid < 128) {
        int gr = r0 + tid;
        float rm = dec_f(g_rmax[gr]);
        srm[tid] = rm;
        sthr[tid] = rm - LSE_CUT;
        #pragma unroll
        for (int t = 0; t < 4; t++)
            sp[tid][t] = g_S[(size_t)gr * NT + gr * 4 + t];
    }
    __syncthreads();

    // ---- row sub-pass: thread = (row, 64-col half) ----
    {
        const int r = tid >> 1, half = tid & 1;
        const float p0 = sp[r][0], p1 = sp[r][1], p2 = sp[r][2], p3 = sp[r][3];
        const float rm = srm[r], thr = sthr[r];
        int c0n = 0, c1n = 0, c2n = 0, c3n = 0;
        float rs = 0.f;
        const float* tp = &tile[r * SPAD + half * 64];
        #pragma unroll 8
        for (int i = 0; i < 32; i++) {
            float2 xv = *reinterpret_cast<const float2*>(tp + i * 2);
            c0n += (xv.x > p0) + (xv.y > p0);
            c1n += (xv.x > p1) + (xv.y > p1);
            c2n += (xv.x > p2) + (xv.y > p2);
            c3n += (xv.x > p3) + (xv.y > p3);
            if (xv.x > thr) rs += expf(xv.x - rm);
            if (xv.y > thr) rs += expf(xv.y - rm);
        }
        scnt2[half][r][0] = c0n; scnt2[half][r][1] = c1n;
        scnt2[half][r][2] = c2n; scnt2[half][r][3] = c3n;
        srs2[half][r] = rs;
    }

    // ---- col sub-pass: thread = (col, 64-row half) ----
    {
        const int c = tid & 127, halfr = tid >> 7;
        const float cm = dec_f(g_cmax[c0 + c]);
        const float cthr = cm - LSE_CUT;
        float cs = 0.f;
        const float* tp = &tile[(halfr * 64) * SPAD + c];
        #pragma unroll 8
        for (int r = 0; r < 64; r++) {
            float x = tp[r * SPAD];
            if (x > cthr) cs += expf(x - cm);
        }
        scs2[halfr][c] = cs;
    }
    __syncthreads();

    if (tid < 128) {
        g_cpart[rt][c0 + tid] = scs2[0][tid] + scs2[1][tid];
        g_rspart[ct][r0 + tid] = srs2[0][tid] + srs2[1][tid];
        #pragma unroll
        for (int t = 0; t < 4; t++)
            atomicAdd(&g_cnt[r0 + tid][t], scnt2[0][tid][t] + scnt2[1][tid][t]);
    }
}

// ===========================================================================
// K4: per-row finalize
__global__ __launch_bounds__(256)
void rowfin_kernel() {
    int i = blockIdx.x * 256 + threadIdx.x;
    if (i >= N) return;

    float p[4];
    #pragma unroll
    for (int t = 0; t < 4; t++) p[t] = g_S[(size_t)i * NT + i * 4 + t];
    float rm = dec_f(g_rmax[i]);

    float rsum = 0.f;
    for (int ct = 0; ct < CTILE; ct++) rsum += g_rspart[ct][i];

    float pm = fmaxf(fmaxf(p[0], p[1]), fmaxf(p[2], p[3]));
    float nom = pm + logf(expf(p[0] - pm) + expf(p[1] - pm) +
                          expf(p[2] - pm) + expf(p[3] - pm));

    float cmv[4], M = rm;
    #pragma unroll
    for (int t = 0; t < 4; t++) {
        cmv[t] = dec_f(g_cmax[i * 4 + t]);
        M = fmaxf(M, cmv[t]);
    }
    float tot = rsum * expf(rm - M);
    #pragma unroll
    for (int t = 0; t < 4; t++) {
        float cs = 0.f;
        for (int rt = 0; rt < RTILE; rt++) cs += g_cpart[rt][i * 4 + t];
        tot += cs * expf(cmv[t] - M);
    }
    float denom = M + logf(tot);

    float r1 = 0.f, r5 = 0.f, r10 = 0.f, ar = 0.f;
    #pragma unroll
    for (int t = 0; t < 4; t++) {
        int rk = g_cnt[i][t];
        r1  += (rk < 1);
        r5  += (rk < 5);
        r10 += (rk < 10);
        ar  += (float)rk;
    }
    g_rowout[i][0] = denom - nom;
    g_rowout[i][1] = r1  * 0.25f;
    g_rowout[i][2] = r5  * 0.25f;
    g_rowout[i][3] = r10 * 0.25f;
    g_rowout[i][4] = ar  * 0.25f;
}

// ===========================================================================
// K5: deterministic means
__global__ __launch_bounds__(256)
void final_kernel(float* __restrict__ out) {
    __shared__ double sacc[5][256];
    int tid = threadIdx.x;
    double a[5] = {0, 0, 0, 0, 0};
    for (int i = tid; i < N; i += 256)
        #pragma unroll
        for (int q = 0; q < 5; q++) a[q] += (double)g_rowout[i][q];
    #pragma unroll
    for (int q = 0; q < 5; q++) sacc[q][tid] = a[q];
    __syncthreads();
    for (int off = 128; off > 0; off >>= 1) {
        if (tid < off)
            #pragma unroll
            for (int q = 0; q < 5; q++) sacc[q][tid] += sacc[q][tid + off];
        __syncthreads();
    }
    if (tid == 0)
        #pragma unroll
        for (int q = 0; q < 5; q++) out[q] = (float)(sacc[q][0] / (double)N);
}

// ===========================================================================
extern "C" void kernel_launch(void* const* d_in, const int* in_sizes, int n_in,
                              void* d_out, int out_size) {
    const float* v = (const float*)d_in[0];   // [4096, 256]
    const float* t = (const float*)d_in[1];   // [16384, 256]
    (void)in_sizes; (void)n_in; (void)out_size;

    static int attr_done = 0;
    if (!attr_done) {
        cudaFuncSetAttribute(gemm_mma, cudaFuncAttributeMaxDynamicSharedMemorySize, GEMM_SMEM);
        cudaFuncSetAttribute(stats_kernel, cudaFuncAttributeMaxDynamicSharedMemorySize, STAT_SMEM);
        attr_done = 1;
    }

    init_kernel<<<(NT + 255) / 256, 256>>>();
    split_kernel<<<(NA + NB + 255) / 256, 256>>>(v, t);
    gemm_mma<<<dim3(CTILE, RTILE), 256, GEMM_SMEM>>>();
    stats_kernel<<<dim3(CTILE, RTILE), 256, STAT_SMEM>>>();
    rowfin_kernel<<<(N + 255) / 256, 256>>>();
    final_kernel<<<1, 256>>>((float*)d_out);
}